// round 1
// baseline (speedup 1.0000x reference)
#include <cuda_runtime.h>
#include <cuda_bf16.h>
#include <math.h>

// Problem constants
#define BATCH 2
#define SEQ   2048
#define DIM   1024
#define NHEAD 16
#define HDIM  64
#define MROWS (BATCH*SEQ)   // 4096

// Scratch buffers (allocation-free rule: static device globals)
__device__ float g_q[MROWS * DIM];
__device__ float g_k[MROWS * DIM];
__device__ float g_v[MROWS * DIM];
__device__ float g_attn[MROWS * DIM];

// ---------------------------------------------------------------------------
// GEMM: C[M,N] = A[M,K] @ W[N,K]^T + bias[N]
// BM=BN=64, BK=16, 256 threads, 4x4 microtile per thread.
// ---------------------------------------------------------------------------
#define BM 64
#define BN 64
#define BK 16

__global__ __launch_bounds__(256) void gemm_bias_kernel(
    const float* __restrict__ A, const float* __restrict__ W,
    const float* __restrict__ bias, float* __restrict__ C,
    int M, int N, int K)
{
    __shared__ float As[BK][BM];
    __shared__ float Bs[BK][BN];

    const int bm = blockIdx.y * BM;
    const int bn = blockIdx.x * BN;
    const int tid = threadIdx.x;
    const int tx = tid & 15;       // 0..15 -> N microtile
    const int ty = tid >> 4;       // 0..15 -> M microtile

    // loader mapping: 256 threads load 64x16 tile; each thread one float4
    const int lrow = tid >> 2;         // 0..63
    const int lvec = (tid & 3) * 4;    // 0,4,8,12

    float acc[4][4];
#pragma unroll
    for (int i = 0; i < 4; i++)
#pragma unroll
        for (int j = 0; j < 4; j++) acc[i][j] = 0.f;

    const float* aptr = A + (size_t)(bm + lrow) * K + lvec;
    const float* wptr = W + (size_t)(bn + lrow) * K + lvec;

    for (int k0 = 0; k0 < K; k0 += BK) {
        float4 a = *(const float4*)(aptr + k0);
        float4 w = *(const float4*)(wptr + k0);
        As[lvec + 0][lrow] = a.x; As[lvec + 1][lrow] = a.y;
        As[lvec + 2][lrow] = a.z; As[lvec + 3][lrow] = a.w;
        Bs[lvec + 0][lrow] = w.x; Bs[lvec + 1][lrow] = w.y;
        Bs[lvec + 2][lrow] = w.z; Bs[lvec + 3][lrow] = w.w;
        __syncthreads();

#pragma unroll
        for (int kk = 0; kk < BK; kk++) {
            float4 ra = *(const float4*)&As[kk][ty * 4];
            float4 rb = *(const float4*)&Bs[kk][tx * 4];
            float a0 = ra.x, a1 = ra.y, a2 = ra.z, a3 = ra.w;
            float b0 = rb.x, b1 = rb.y, b2 = rb.z, b3 = rb.w;
            acc[0][0] += a0 * b0; acc[0][1] += a0 * b1; acc[0][2] += a0 * b2; acc[0][3] += a0 * b3;
            acc[1][0] += a1 * b0; acc[1][1] += a1 * b1; acc[1][2] += a1 * b2; acc[1][3] += a1 * b3;
            acc[2][0] += a2 * b0; acc[2][1] += a2 * b1; acc[2][2] += a2 * b2; acc[2][3] += a2 * b3;
            acc[3][0] += a3 * b0; acc[3][1] += a3 * b1; acc[3][2] += a3 * b2; acc[3][3] += a3 * b3;
        }
        __syncthreads();
    }

    const float4 bb = *(const float4*)(bias + bn + tx * 4);
#pragma unroll
    for (int i = 0; i < 4; i++) {
        float4 out;
        out.x = acc[i][0] + bb.x;
        out.y = acc[i][1] + bb.y;
        out.z = acc[i][2] + bb.z;
        out.w = acc[i][3] + bb.w;
        *(float4*)(C + (size_t)(bm + ty * 4 + i) * N + bn + tx * 4) = out;
    }
}

// ---------------------------------------------------------------------------
// RMSNorm in-place over rows of length DIM=1024. One block (256 thr) per row.
// ---------------------------------------------------------------------------
__global__ __launch_bounds__(256) void rmsnorm_kernel(
    float* __restrict__ x, const float* __restrict__ w)
{
    const int row = blockIdx.x;
    float* p = x + (size_t)row * DIM;
    const int t = threadIdx.x;

    float4 v = *(const float4*)(p + t * 4);
    float ss = v.x * v.x + v.y * v.y + v.z * v.z + v.w * v.w;

    // warp reduce
#pragma unroll
    for (int off = 16; off > 0; off >>= 1)
        ss += __shfl_xor_sync(0xFFFFFFFFu, ss, off);

    __shared__ float red[8];
    if ((t & 31) == 0) red[t >> 5] = ss;
    __syncthreads();
    float total;
    {
        float r = (t < 8) ? red[t] : 0.f;
#pragma unroll
        for (int off = 4; off > 0; off >>= 1)
            r += __shfl_xor_sync(0xFFFFFFFFu, r, off);
        if (t == 0) red[0] = r;
    }
    __syncthreads();
    total = red[0];

    const float norm = rsqrtf(total * (1.0f / DIM) + 1e-6f);
    const float4 w4 = *(const float4*)(w + t * 4);
    v.x = v.x * norm * w4.x;
    v.y = v.y * norm * w4.y;
    v.z = v.z * norm * w4.z;
    v.w = v.w * norm * w4.w;
    *(float4*)(p + t * 4) = v;
}

// ---------------------------------------------------------------------------
// Flash attention, fp32. Grid: (S/128, NHEAD, BATCH). Block: 128 threads,
// one query per thread. K/V tiles of 64 keys in smem (broadcast reads).
// ---------------------------------------------------------------------------
__global__ __launch_bounds__(128) void attn_kernel(
    const float* __restrict__ q, const float* __restrict__ k,
    const float* __restrict__ v, float* __restrict__ out)
{
    const int t  = threadIdx.x;
    const int qi = blockIdx.x * 128 + t;
    const int h  = blockIdx.y;
    const int b  = blockIdx.z;
    const float scale = 0.125f;   // 1/sqrt(64)

    __shared__ float Ks[64][HDIM];
    __shared__ float Vs[64][HDIM];

    float qreg[HDIM];
    {
        const float4* qp = (const float4*)(q + ((size_t)b * SEQ + qi) * DIM + h * HDIM);
#pragma unroll
        for (int c4 = 0; c4 < 16; c4++) {
            float4 x = qp[c4];
            qreg[c4 * 4 + 0] = x.x; qreg[c4 * 4 + 1] = x.y;
            qreg[c4 * 4 + 2] = x.z; qreg[c4 * 4 + 3] = x.w;
        }
    }

    float m = -1e30f, l = 0.f;
    float o[HDIM];
#pragma unroll
    for (int c = 0; c < HDIM; c++) o[c] = 0.f;

    for (int k0 = 0; k0 < SEQ; k0 += 64) {
        __syncthreads();   // protect previous tile reads
        // cooperative load of K,V tiles: 64 rows x 16 float4 = 1024 float4 each
        for (int i = t; i < 64 * 16; i += 128) {
            int r  = i >> 4;
            int c4 = i & 15;
            size_t src = ((size_t)b * SEQ + k0 + r) * DIM + h * HDIM + c4 * 4;
            *(float4*)&Ks[r][c4 * 4] = *(const float4*)(k + src);
            *(float4*)&Vs[r][c4 * 4] = *(const float4*)(v + src);
        }
        __syncthreads();

        // process 64 keys in chunks of 16 (register pressure control)
#pragma unroll 1
        for (int j0 = 0; j0 < 64; j0 += 16) {
            float s[16];
            float cmax = -1e30f;
#pragma unroll
            for (int j = 0; j < 16; j++) {
                const float4* kp = (const float4*)Ks[j0 + j];
                float acc = 0.f;
#pragma unroll
                for (int c4 = 0; c4 < 16; c4++) {
                    float4 kv = kp[c4];
                    acc += qreg[c4 * 4 + 0] * kv.x;
                    acc += qreg[c4 * 4 + 1] * kv.y;
                    acc += qreg[c4 * 4 + 2] * kv.z;
                    acc += qreg[c4 * 4 + 3] * kv.w;
                }
                s[j] = acc * scale;
                cmax = fmaxf(cmax, s[j]);
            }
            float mnew  = fmaxf(m, cmax);
            float alpha = __expf(m - mnew);
            l *= alpha;
#pragma unroll
            for (int c = 0; c < HDIM; c++) o[c] *= alpha;
#pragma unroll
            for (int j = 0; j < 16; j++) {
                float p = __expf(s[j] - mnew);
                l += p;
                const float4* vp = (const float4*)Vs[j0 + j];
#pragma unroll
                for (int c4 = 0; c4 < 16; c4++) {
                    float4 vv = vp[c4];
                    o[c4 * 4 + 0] += p * vv.x;
                    o[c4 * 4 + 1] += p * vv.y;
                    o[c4 * 4 + 2] += p * vv.z;
                    o[c4 * 4 + 3] += p * vv.w;
                }
            }
            m = mnew;
        }
    }

    const float inv = 1.f / l;
    float4* op = (float4*)(out + ((size_t)b * SEQ + qi) * DIM + h * HDIM);
#pragma unroll
    for (int c4 = 0; c4 < 16; c4++) {
        float4 x;
        x.x = o[c4 * 4 + 0] * inv;
        x.y = o[c4 * 4 + 1] * inv;
        x.z = o[c4 * 4 + 2] * inv;
        x.w = o[c4 * 4 + 3] * inv;
        op[c4] = x;
    }
}

// ---------------------------------------------------------------------------
// Launch
// ---------------------------------------------------------------------------
extern "C" void kernel_launch(void* const* d_in, const int* in_sizes, int n_in,
                              void* d_out, int out_size)
{
    const float* x   = (const float*)d_in[0];
    const float* Wq  = (const float*)d_in[1];
    const float* bq  = (const float*)d_in[2];
    const float* Wk  = (const float*)d_in[3];
    const float* bk  = (const float*)d_in[4];
    const float* Wv  = (const float*)d_in[5];
    const float* bv  = (const float*)d_in[6];
    const float* Wo  = (const float*)d_in[7];
    const float* bo  = (const float*)d_in[8];
    const float* nqw = (const float*)d_in[9];
    const float* nkw = (const float*)d_in[10];
    float* out = (float*)d_out;

    float *dq, *dk, *dv, *dattn;
    cudaGetSymbolAddress((void**)&dq,    g_q);
    cudaGetSymbolAddress((void**)&dk,    g_k);
    cudaGetSymbolAddress((void**)&dv,    g_v);
    cudaGetSymbolAddress((void**)&dattn, g_attn);

    dim3 ggrid(DIM / BN, MROWS / BM);   // (16, 64)
    gemm_bias_kernel<<<ggrid, 256>>>(x, Wq, bq, dq, MROWS, DIM, DIM);
    gemm_bias_kernel<<<ggrid, 256>>>(x, Wk, bk, dk, MROWS, DIM, DIM);
    gemm_bias_kernel<<<ggrid, 256>>>(x, Wv, bv, dv, MROWS, DIM, DIM);

    rmsnorm_kernel<<<MROWS, 256>>>(dq, nqw);
    rmsnorm_kernel<<<MROWS, 256>>>(dk, nkw);

    dim3 agrid(SEQ / 128, NHEAD, BATCH);
    attn_kernel<<<agrid, 128>>>(dq, dk, dv, dattn);

    gemm_bias_kernel<<<ggrid, 256>>>(dattn, Wo, bo, out, MROWS, DIM, DIM);
}

// round 3
// speedup vs baseline: 1.4683x; 1.4683x over previous
#include <cuda_runtime.h>
#include <cuda_bf16.h>
#include <math.h>
#include <stdint.h>

// Problem constants
#define BATCH 2
#define SEQ   2048
#define DIM   1024
#define NHEAD 16
#define HDIM  64
#define MROWS (BATCH*SEQ)   // 4096

// Scratch buffers (allocation-free rule: static device globals)
__device__ float g_q[MROWS * DIM];
__device__ float g_k[MROWS * DIM];
__device__ float g_v[MROWS * DIM];
__device__ float g_attn[MROWS * DIM];

// ---------------------------------------------------------------------------
// tf32 tensor-core GEMM: C[M,N] = A[M,K] @ W[N,K]^T + bias[N]
// Tiles: 128x128x32, 256 threads = 8 warps (2 M x 4 N), 64x32 per warp.
// mma.sync.aligned.m16n8k8.row.col.f32.tf32.tf32.f32
// smem row stride 36 words -> (4r+c)%32 distinct across lanes: conflict-free
// fragment loads.
// ---------------------------------------------------------------------------
#define GBM 128
#define GBN 128
#define GBK 32
#define KSTRIDE 36

__device__ __forceinline__ uint32_t f2tf32(float f) {
    uint32_t u;
    asm("cvt.rna.tf32.f32 %0, %1;" : "=r"(u) : "f"(f));
    return u;
}

__device__ __forceinline__ void mma_tf32(float* d, const uint32_t* a,
                                         const uint32_t* b, const float* c) {
    asm volatile(
        "mma.sync.aligned.m16n8k8.row.col.f32.tf32.tf32.f32 "
        "{%0,%1,%2,%3}, {%4,%5,%6,%7}, {%8,%9}, {%10,%11,%12,%13};\n"
        : "=f"(d[0]), "=f"(d[1]), "=f"(d[2]), "=f"(d[3])
        : "r"(a[0]), "r"(a[1]), "r"(a[2]), "r"(a[3]),
          "r"(b[0]), "r"(b[1]),
          "f"(c[0]), "f"(c[1]), "f"(c[2]), "f"(c[3]));
}

__global__ __launch_bounds__(256) void gemm_tf32_kernel(
    const float* __restrict__ A, const float* __restrict__ W,
    const float* __restrict__ bias, float* __restrict__ C,
    int M, int N, int K)
{
    __shared__ uint32_t As[GBM][KSTRIDE];
    __shared__ uint32_t Bs[GBN][KSTRIDE];

    const int tid  = threadIdx.x;
    const int bm   = blockIdx.y * GBM;
    const int bn   = blockIdx.x * GBN;
    const int warp = tid >> 5;
    const int lane = tid & 31;
    const int wm   = (warp >> 2) * 64;   // 0 or 64
    const int wn   = (warp & 3) * 32;    // 0,32,64,96
    const int gr   = lane >> 2;          // 0..7
    const int tg   = lane & 3;           // 0..3

    // loader mapping: 2 threads per row, 16 floats (4 float4) each
    const int lrow = tid >> 1;           // 0..127
    const int lcol = (tid & 1) * 16;     // 0 or 16
    const float* ag = A + (size_t)(bm + lrow) * K + lcol;
    const float* wg = W + (size_t)(bn + lrow) * K + lcol;

    float acc[4][4][4];
#pragma unroll
    for (int i = 0; i < 4; i++)
#pragma unroll
        for (int j = 0; j < 4; j++)
#pragma unroll
            for (int c = 0; c < 4; c++) acc[i][j][c] = 0.f;

    // prefetch tile 0 into registers
    float4 ra[4], rb[4];
#pragma unroll
    for (int c = 0; c < 4; c++) {
        ra[c] = *(const float4*)(ag + c * 4);
        rb[c] = *(const float4*)(wg + c * 4);
    }

    for (int k0 = 0; k0 < K; k0 += GBK) {
        __syncthreads();   // protect previous tile reads
        // cvt.rna -> tf32, store to smem
#pragma unroll
        for (int c = 0; c < 4; c++) {
            uint32_t* ap = &As[lrow][lcol + c * 4];
            ap[0] = f2tf32(ra[c].x); ap[1] = f2tf32(ra[c].y);
            ap[2] = f2tf32(ra[c].z); ap[3] = f2tf32(ra[c].w);
            uint32_t* bp = &Bs[lrow][lcol + c * 4];
            bp[0] = f2tf32(rb[c].x); bp[1] = f2tf32(rb[c].y);
            bp[2] = f2tf32(rb[c].z); bp[3] = f2tf32(rb[c].w);
        }
        __syncthreads();

        // prefetch next tile (overlaps with compute below)
        if (k0 + GBK < K) {
#pragma unroll
            for (int c = 0; c < 4; c++) {
                ra[c] = *(const float4*)(ag + k0 + GBK + c * 4);
                rb[c] = *(const float4*)(wg + k0 + GBK + c * 4);
            }
        }

        // 4 k-steps of 8
#pragma unroll
        for (int ks = 0; ks < 4; ks++) {
            const int kk = ks * 8;
            uint32_t af[4][4], bf[4][2];
#pragma unroll
            for (int i = 0; i < 4; i++) {
                const int r = wm + i * 16 + gr;
                af[i][0] = As[r][kk + tg];
                af[i][1] = As[r + 8][kk + tg];
                af[i][2] = As[r][kk + tg + 4];
                af[i][3] = As[r + 8][kk + tg + 4];
            }
#pragma unroll
            for (int j = 0; j < 4; j++) {
                const int n = wn + j * 8 + gr;
                bf[j][0] = Bs[n][kk + tg];
                bf[j][1] = Bs[n][kk + tg + 4];
            }
#pragma unroll
            for (int i = 0; i < 4; i++)
#pragma unroll
                for (int j = 0; j < 4; j++)
                    mma_tf32(acc[i][j], af[i], bf[j], acc[i][j]);
        }
    }

    // epilogue: bias + store
#pragma unroll
    for (int i = 0; i < 4; i++) {
#pragma unroll
        for (int j = 0; j < 4; j++) {
            const int row = bm + wm + i * 16 + gr;
            const int col = bn + wn + j * 8 + 2 * tg;
            const float2 b01 = *(const float2*)(bias + col);
            float2 o0, o1;
            o0.x = acc[i][j][0] + b01.x;
            o0.y = acc[i][j][1] + b01.y;
            o1.x = acc[i][j][2] + b01.x;
            o1.y = acc[i][j][3] + b01.y;
            *(float2*)(C + (size_t)row * N + col)       = o0;
            *(float2*)(C + (size_t)(row + 8) * N + col) = o1;
        }
    }
}

// ---------------------------------------------------------------------------
// RMSNorm in-place over rows of length DIM=1024. One block (256 thr) per row.
// ---------------------------------------------------------------------------
__global__ __launch_bounds__(256) void rmsnorm_kernel(
    float* __restrict__ x, const float* __restrict__ w)
{
    const int row = blockIdx.x;
    float* p = x + (size_t)row * DIM;
    const int t = threadIdx.x;

    float4 v = *(const float4*)(p + t * 4);
    float ss = v.x * v.x + v.y * v.y + v.z * v.z + v.w * v.w;

#pragma unroll
    for (int off = 16; off > 0; off >>= 1)
        ss += __shfl_xor_sync(0xFFFFFFFFu, ss, off);

    __shared__ float red[8];
    if ((t & 31) == 0) red[t >> 5] = ss;
    __syncthreads();
    float total;
    {
        float r = (t < 8) ? red[t] : 0.f;
#pragma unroll
        for (int off = 4; off > 0; off >>= 1)
            r += __shfl_xor_sync(0xFFFFFFFFu, r, off);
        if (t == 0) red[0] = r;
    }
    __syncthreads();
    total = red[0];

    const float norm = rsqrtf(total * (1.0f / DIM) + 1e-6f);
    const float4 w4 = *(const float4*)(w + t * 4);
    v.x = v.x * norm * w4.x;
    v.y = v.y * norm * w4.y;
    v.z = v.z * norm * w4.z;
    v.w = v.w * norm * w4.w;
    *(float4*)(p + t * 4) = v;
}

// ---------------------------------------------------------------------------
// Flash attention, fp32. Grid: (S/128, NHEAD, BATCH). Block: 128 threads,
// one query per thread. K/V tiles of 64 keys in smem (broadcast reads).
// ---------------------------------------------------------------------------
__global__ __launch_bounds__(128) void attn_kernel(
    const float* __restrict__ q, const float* __restrict__ k,
    const float* __restrict__ v, float* __restrict__ out)
{
    const int t  = threadIdx.x;
    const int qi = blockIdx.x * 128 + t;
    const int h  = blockIdx.y;
    const int b  = blockIdx.z;
    const float scale = 0.125f;   // 1/sqrt(64)

    __shared__ float Ks[64][HDIM];
    __shared__ float Vs[64][HDIM];

    float qreg[HDIM];
    {
        const float4* qp = (const float4*)(q + ((size_t)b * SEQ + qi) * DIM + h * HDIM);
#pragma unroll
        for (int c4 = 0; c4 < 16; c4++) {
            float4 x = qp[c4];
            qreg[c4 * 4 + 0] = x.x; qreg[c4 * 4 + 1] = x.y;
            qreg[c4 * 4 + 2] = x.z; qreg[c4 * 4 + 3] = x.w;
        }
    }

    float m = -1e30f, l = 0.f;
    float o[HDIM];
#pragma unroll
    for (int c = 0; c < HDIM; c++) o[c] = 0.f;

    for (int k0 = 0; k0 < SEQ; k0 += 64) {
        __syncthreads();
        for (int i = t; i < 64 * 16; i += 128) {
            int r  = i >> 4;
            int c4 = i & 15;
            size_t src = ((size_t)b * SEQ + k0 + r) * DIM + h * HDIM + c4 * 4;
            *(float4*)&Ks[r][c4 * 4] = *(const float4*)(k + src);
            *(float4*)&Vs[r][c4 * 4] = *(const float4*)(v + src);
        }
        __syncthreads();

#pragma unroll 1
        for (int j0 = 0; j0 < 64; j0 += 16) {
            float s[16];
            float cmax = -1e30f;
#pragma unroll
            for (int j = 0; j < 16; j++) {
                const float4* kp = (const float4*)Ks[j0 + j];
                float acc = 0.f;
#pragma unroll
                for (int c4 = 0; c4 < 16; c4++) {
                    float4 kv = kp[c4];
                    acc += qreg[c4 * 4 + 0] * kv.x;
                    acc += qreg[c4 * 4 + 1] * kv.y;
                    acc += qreg[c4 * 4 + 2] * kv.z;
                    acc += qreg[c4 * 4 + 3] * kv.w;
                }
                s[j] = acc * scale;
                cmax = fmaxf(cmax, s[j]);
            }
            float mnew  = fmaxf(m, cmax);
            float alpha = __expf(m - mnew);
            l *= alpha;
#pragma unroll
            for (int c = 0; c < HDIM; c++) o[c] *= alpha;
#pragma unroll
            for (int j = 0; j < 16; j++) {
                float p = __expf(s[j] - mnew);
                l += p;
                const float4* vp = (const float4*)Vs[j0 + j];
#pragma unroll
                for (int c4 = 0; c4 < 16; c4++) {
                    float4 vv = vp[c4];
                    o[c4 * 4 + 0] += p * vv.x;
                    o[c4 * 4 + 1] += p * vv.y;
                    o[c4 * 4 + 2] += p * vv.z;
                    o[c4 * 4 + 3] += p * vv.w;
                }
            }
            m = mnew;
        }
    }

    const float inv = 1.f / l;
    float4* op = (float4*)(out + ((size_t)b * SEQ + qi) * DIM + h * HDIM);
#pragma unroll
    for (int c4 = 0; c4 < 16; c4++) {
        float4 x;
        x.x = o[c4 * 4 + 0] * inv;
        x.y = o[c4 * 4 + 1] * inv;
        x.z = o[c4 * 4 + 2] * inv;
        x.w = o[c4 * 4 + 3] * inv;
        op[c4] = x;
    }
}

// ---------------------------------------------------------------------------
// Launch
// ---------------------------------------------------------------------------
extern "C" void kernel_launch(void* const* d_in, const int* in_sizes, int n_in,
                              void* d_out, int out_size)
{
    const float* x   = (const float*)d_in[0];
    const float* Wq  = (const float*)d_in[1];
    const float* bq  = (const float*)d_in[2];
    const float* Wk  = (const float*)d_in[3];
    const float* bk  = (const float*)d_in[4];
    const float* Wv  = (const float*)d_in[5];
    const float* bv  = (const float*)d_in[6];
    const float* Wo  = (const float*)d_in[7];
    const float* bo  = (const float*)d_in[8];
    const float* nqw = (const float*)d_in[9];
    const float* nkw = (const float*)d_in[10];
    float* out = (float*)d_out;

    float *dq, *dk, *dv, *dattn;
    cudaGetSymbolAddress((void**)&dq,    g_q);
    cudaGetSymbolAddress((void**)&dk,    g_k);
    cudaGetSymbolAddress((void**)&dv,    g_v);
    cudaGetSymbolAddress((void**)&dattn, g_attn);

    dim3 ggrid(DIM / GBN, MROWS / GBM);   // (8, 32)
    gemm_tf32_kernel<<<ggrid, 256>>>(x, Wq, bq, dq, MROWS, DIM, DIM);
    gemm_tf32_kernel<<<ggrid, 256>>>(x, Wk, bk, dk, MROWS, DIM, DIM);
    gemm_tf32_kernel<<<ggrid, 256>>>(x, Wv, bv, dv, MROWS, DIM, DIM);

    rmsnorm_kernel<<<MROWS, 256>>>(dq, nqw);
    rmsnorm_kernel<<<MROWS, 256>>>(dk, nkw);

    dim3 agrid(SEQ / 128, NHEAD, BATCH);
    attn_kernel<<<agrid, 128>>>(dq, dk, dv, dattn);

    gemm_tf32_kernel<<<ggrid, 256>>>(dattn, Wo, bo, out, MROWS, DIM, DIM);
}

// round 4
// speedup vs baseline: 2.6246x; 1.7875x over previous
#include <cuda_runtime.h>
#include <cuda_bf16.h>
#include <math.h>
#include <stdint.h>

// Problem constants
#define BATCH 2
#define SEQ   2048
#define DIM   1024
#define NHEAD 16
#define HDIM  64
#define MROWS (BATCH*SEQ)   // 4096

// Scratch buffers (allocation-free rule: static device globals)
__device__ float g_q[MROWS * DIM];
__device__ float g_k[MROWS * DIM];
__device__ float g_v[MROWS * DIM];
__device__ float g_attn[MROWS * DIM];

__device__ __forceinline__ uint32_t f2tf32(float f) {
    uint32_t u;
    asm("cvt.rna.tf32.f32 %0, %1;" : "=r"(u) : "f"(f));
    return u;
}

__device__ __forceinline__ void mma_tf32(float* d, const uint32_t* a,
                                         const uint32_t* b, const float* c) {
    asm volatile(
        "mma.sync.aligned.m16n8k8.row.col.f32.tf32.tf32.f32 "
        "{%0,%1,%2,%3}, {%4,%5,%6,%7}, {%8,%9}, {%10,%11,%12,%13};\n"
        : "=f"(d[0]), "=f"(d[1]), "=f"(d[2]), "=f"(d[3])
        : "r"(a[0]), "r"(a[1]), "r"(a[2]), "r"(a[3]),
          "r"(b[0]), "r"(b[1]),
          "f"(c[0]), "f"(c[1]), "f"(c[2]), "f"(c[3]));
}

// ---------------------------------------------------------------------------
// tf32 tensor-core GEMM: C[M,N] = A[M,K] @ W[N,K]^T + bias[N]
// Tiles: 128x128x32, 256 threads = 8 warps (2 M x 4 N), 64x32 per warp.
// ---------------------------------------------------------------------------
#define GBM 128
#define GBN 128
#define GBK 32
#define KSTRIDE 36

__device__ __forceinline__ void gemm_tf32_body(
    const float* __restrict__ A, const float* __restrict__ W,
    const float* __restrict__ bias, float* __restrict__ C,
    int M, int N, int K, int bx, int by)
{
    __shared__ uint32_t As[GBM][KSTRIDE];
    __shared__ uint32_t Bs[GBN][KSTRIDE];

    const int tid  = threadIdx.x;
    const int bm   = by * GBM;
    const int bn   = bx * GBN;
    const int warp = tid >> 5;
    const int lane = tid & 31;
    const int wm   = (warp >> 2) * 64;
    const int wn   = (warp & 3) * 32;
    const int gr   = lane >> 2;
    const int tg   = lane & 3;

    const int lrow = tid >> 1;
    const int lcol = (tid & 1) * 16;
    const float* ag = A + (size_t)(bm + lrow) * K + lcol;
    const float* wg = W + (size_t)(bn + lrow) * K + lcol;

    float acc[4][4][4];
#pragma unroll
    for (int i = 0; i < 4; i++)
#pragma unroll
        for (int j = 0; j < 4; j++)
#pragma unroll
            for (int c = 0; c < 4; c++) acc[i][j][c] = 0.f;

    float4 ra[4], rb[4];
#pragma unroll
    for (int c = 0; c < 4; c++) {
        ra[c] = *(const float4*)(ag + c * 4);
        rb[c] = *(const float4*)(wg + c * 4);
    }

    for (int k0 = 0; k0 < K; k0 += GBK) {
        __syncthreads();
#pragma unroll
        for (int c = 0; c < 4; c++) {
            uint32_t* ap = &As[lrow][lcol + c * 4];
            ap[0] = f2tf32(ra[c].x); ap[1] = f2tf32(ra[c].y);
            ap[2] = f2tf32(ra[c].z); ap[3] = f2tf32(ra[c].w);
            uint32_t* bp = &Bs[lrow][lcol + c * 4];
            bp[0] = f2tf32(rb[c].x); bp[1] = f2tf32(rb[c].y);
            bp[2] = f2tf32(rb[c].z); bp[3] = f2tf32(rb[c].w);
        }
        __syncthreads();

        if (k0 + GBK < K) {
#pragma unroll
            for (int c = 0; c < 4; c++) {
                ra[c] = *(const float4*)(ag + k0 + GBK + c * 4);
                rb[c] = *(const float4*)(wg + k0 + GBK + c * 4);
            }
        }

#pragma unroll
        for (int ks = 0; ks < 4; ks++) {
            const int kk = ks * 8;
            uint32_t af[4][4], bf[4][2];
#pragma unroll
            for (int i = 0; i < 4; i++) {
                const int r = wm + i * 16 + gr;
                af[i][0] = As[r][kk + tg];
                af[i][1] = As[r + 8][kk + tg];
                af[i][2] = As[r][kk + tg + 4];
                af[i][3] = As[r + 8][kk + tg + 4];
            }
#pragma unroll
            for (int j = 0; j < 4; j++) {
                const int n = wn + j * 8 + gr;
                bf[j][0] = Bs[n][kk + tg];
                bf[j][1] = Bs[n][kk + tg + 4];
            }
#pragma unroll
            for (int i = 0; i < 4; i++)
#pragma unroll
                for (int j = 0; j < 4; j++)
                    mma_tf32(acc[i][j], af[i], bf[j], acc[i][j]);
        }
    }

#pragma unroll
    for (int i = 0; i < 4; i++) {
#pragma unroll
        for (int j = 0; j < 4; j++) {
            const int row = bm + wm + i * 16 + gr;
            const int col = bn + wn + j * 8 + 2 * tg;
            const float2 b01 = *(const float2*)(bias + col);
            float2 o0, o1;
            o0.x = acc[i][j][0] + b01.x;
            o0.y = acc[i][j][1] + b01.y;
            o1.x = acc[i][j][2] + b01.x;
            o1.y = acc[i][j][3] + b01.y;
            *(float2*)(C + (size_t)row * N + col)       = o0;
            *(float2*)(C + (size_t)(row + 8) * N + col) = o1;
        }
    }
}

__global__ __launch_bounds__(256) void gemm_tf32_kernel(
    const float* __restrict__ A, const float* __restrict__ W,
    const float* __restrict__ bias, float* __restrict__ C,
    int M, int N, int K)
{
    gemm_tf32_body(A, W, bias, C, M, N, K, blockIdx.x, blockIdx.y);
}

// Fused QKV: blockIdx.z selects which projection (better wave packing)
__global__ __launch_bounds__(256) void gemm_qkv_kernel(
    const float* __restrict__ A,
    const float* __restrict__ Wq, const float* __restrict__ bq,
    const float* __restrict__ Wk, const float* __restrict__ bk,
    const float* __restrict__ Wv, const float* __restrict__ bv,
    float* __restrict__ Cq, float* __restrict__ Ck, float* __restrict__ Cv)
{
    const float* W; const float* b; float* C;
    if (blockIdx.z == 0)      { W = Wq; b = bq; C = Cq; }
    else if (blockIdx.z == 1) { W = Wk; b = bk; C = Ck; }
    else                      { W = Wv; b = bv; C = Cv; }
    gemm_tf32_body(A, W, b, C, MROWS, DIM, DIM, blockIdx.x, blockIdx.y);
}

// ---------------------------------------------------------------------------
// RMSNorm in-place over rows of length DIM=1024. One block (256 thr) per row.
// ---------------------------------------------------------------------------
__global__ __launch_bounds__(256) void rmsnorm_kernel(
    float* __restrict__ x, const float* __restrict__ w)
{
    const int row = blockIdx.x;
    float* p = x + (size_t)row * DIM;
    const int t = threadIdx.x;

    float4 v = *(const float4*)(p + t * 4);
    float ss = v.x * v.x + v.y * v.y + v.z * v.z + v.w * v.w;

#pragma unroll
    for (int off = 16; off > 0; off >>= 1)
        ss += __shfl_xor_sync(0xFFFFFFFFu, ss, off);

    __shared__ float red[8];
    if ((t & 31) == 0) red[t >> 5] = ss;
    __syncthreads();
    float total;
    {
        float r = (t < 8) ? red[t] : 0.f;
#pragma unroll
        for (int off = 4; off > 0; off >>= 1)
            r += __shfl_xor_sync(0xFFFFFFFFu, r, off);
        if (t == 0) red[0] = r;
    }
    __syncthreads();
    total = red[0];

    const float norm = rsqrtf(total * (1.0f / DIM) + 1e-6f);
    const float4 w4 = *(const float4*)(w + t * 4);
    v.x = v.x * norm * w4.x;
    v.y = v.y * norm * w4.y;
    v.z = v.z * norm * w4.z;
    v.w = v.w * norm * w4.w;
    *(float4*)(p + t * 4) = v;
}

// ---------------------------------------------------------------------------
// Tensor-core flash attention (tf32 mma.m16n8k8).
// Grid (SEQ/64, NHEAD, BATCH), 128 threads = 4 warps, 16 Q-rows per warp.
// K stored column-PERMUTED in smem (logical l -> physical 2(l%4)+(l/4) within
// groups of 8) so the QK^T accumulator layout IS the A-fragment layout for the
// PV MMA. V stays in logical order. Softmax is permutation-invariant.
// Strides: Ks 68 (banks 4gr+tg conflict-free), Vs 72 (banks 8tg+gr).
// ---------------------------------------------------------------------------
#define KSTR_K 68
#define KSTR_V 72

__global__ __launch_bounds__(128) void attn_tc_kernel(
    const float* __restrict__ q, const float* __restrict__ k,
    const float* __restrict__ v, float* __restrict__ out)
{
    __shared__ uint32_t Ks[64][KSTR_K];
    __shared__ uint32_t Vs[64][KSTR_V];

    const int tid  = threadIdx.x;
    const int warp = tid >> 5;
    const int lane = tid & 31;
    const int gr   = lane >> 2;
    const int tg   = lane & 3;
    const int h    = blockIdx.y;
    const int b    = blockIdx.z;

    const int r0 = blockIdx.x * 64 + warp * 16 + gr;   // first row of this thread
    const int r1 = r0 + 8;
    const size_t headoff = (size_t)h * HDIM;
    const size_t bbase   = (size_t)b * SEQ;

    // Q fragments, softmax scale folded in (1/sqrt(64) = 0.125)
    uint32_t qf[8][4];
    {
        const float* q0 = q + (bbase + r0) * DIM + headoff;
        const float* q1 = q + (bbase + r1) * DIM + headoff;
#pragma unroll
        for (int j = 0; j < 8; j++) {
            qf[j][0] = f2tf32(q0[8 * j + tg]     * 0.125f);
            qf[j][1] = f2tf32(q1[8 * j + tg]     * 0.125f);
            qf[j][2] = f2tf32(q0[8 * j + tg + 4] * 0.125f);
            qf[j][3] = f2tf32(q1[8 * j + tg + 4] * 0.125f);
        }
    }

    float of[8][4];
#pragma unroll
    for (int nt = 0; nt < 8; nt++)
#pragma unroll
        for (int c = 0; c < 4; c++) of[nt][c] = 0.f;

    float m0 = -1e30f, m1 = -1e30f, l0 = 0.f, l1 = 0.f;

    for (int k0 = 0; k0 < SEQ; k0 += 64) {
        __syncthreads();   // protect previous tile
        // cooperative load: K (permuted, tf32) + V (natural, tf32)
        for (int i = tid; i < 64 * 16; i += 128) {
            const int r  = i >> 4;
            const int c4 = i & 15;
            const int l  = r & 7;
            const int pr = (r & ~7) | (2 * (l & 3) + (l >> 2));
            const size_t src = (bbase + k0 + r) * DIM + headoff + c4 * 4;
            const float4 kv = *(const float4*)(k + src);
            uint4 kw;
            kw.x = f2tf32(kv.x); kw.y = f2tf32(kv.y);
            kw.z = f2tf32(kv.z); kw.w = f2tf32(kv.w);
            *(uint4*)&Ks[pr][c4 * 4] = kw;
            const float4 vv = *(const float4*)(v + src);
            uint4 vw;
            vw.x = f2tf32(vv.x); vw.y = f2tf32(vv.y);
            vw.z = f2tf32(vv.z); vw.w = f2tf32(vv.w);
            *(uint4*)&Vs[r][c4 * 4] = vw;
        }
        __syncthreads();

        // S = Q @ K^T  (16 rows x 64 keys per warp)
        float sacc[8][4];
#pragma unroll
        for (int nt = 0; nt < 8; nt++) {
#pragma unroll
            for (int c = 0; c < 4; c++) sacc[nt][c] = 0.f;
#pragma unroll
            for (int j = 0; j < 8; j++) {
                uint32_t kb[2];
                kb[0] = Ks[8 * nt + gr][8 * j + tg];
                kb[1] = Ks[8 * nt + gr][8 * j + tg + 4];
                mma_tf32(sacc[nt], qf[j], kb, sacc[nt]);
            }
        }

        // online softmax
        float cm0 = -1e30f, cm1 = -1e30f;
#pragma unroll
        for (int nt = 0; nt < 8; nt++) {
            cm0 = fmaxf(cm0, fmaxf(sacc[nt][0], sacc[nt][1]));
            cm1 = fmaxf(cm1, fmaxf(sacc[nt][2], sacc[nt][3]));
        }
        cm0 = fmaxf(cm0, __shfl_xor_sync(0xFFFFFFFFu, cm0, 1));
        cm0 = fmaxf(cm0, __shfl_xor_sync(0xFFFFFFFFu, cm0, 2));
        cm1 = fmaxf(cm1, __shfl_xor_sync(0xFFFFFFFFu, cm1, 1));
        cm1 = fmaxf(cm1, __shfl_xor_sync(0xFFFFFFFFu, cm1, 2));

        const float mn0 = fmaxf(m0, cm0);
        const float mn1 = fmaxf(m1, cm1);
        const float a0 = __expf(m0 - mn0);
        const float a1 = __expf(m1 - mn1);
        m0 = mn0; m1 = mn1;
        l0 *= a0; l1 *= a1;
#pragma unroll
        for (int nt = 0; nt < 8; nt++) {
            of[nt][0] *= a0; of[nt][1] *= a0;
            of[nt][2] *= a1; of[nt][3] *= a1;
        }

        // P = exp(S - m); accumulator layout == A-fragment layout (permutation)
        uint32_t pf[8][4];
#pragma unroll
        for (int nt = 0; nt < 8; nt++) {
            const float p0 = __expf(sacc[nt][0] - m0);
            const float p1 = __expf(sacc[nt][1] - m0);
            const float p2 = __expf(sacc[nt][2] - m1);
            const float p3 = __expf(sacc[nt][3] - m1);
            l0 += p0 + p1;
            l1 += p2 + p3;
            pf[nt][0] = f2tf32(p0);
            pf[nt][1] = f2tf32(p2);   // a1 = row gr+8
            pf[nt][2] = f2tf32(p1);   // a2 = row gr, col tg+4
            pf[nt][3] = f2tf32(p3);
        }

        // O += P @ V   (k-chunks j over keys, n-tiles nt over head dims)
#pragma unroll
        for (int nt = 0; nt < 8; nt++) {
#pragma unroll
            for (int j = 0; j < 8; j++) {
                uint32_t vb[2];
                vb[0] = Vs[8 * j + tg][8 * nt + gr];
                vb[1] = Vs[8 * j + tg + 4][8 * nt + gr];
                mma_tf32(of[nt], pf[j], vb, of[nt]);
            }
        }
    }

    // finalize: reduce l across quad, normalize, store
    l0 += __shfl_xor_sync(0xFFFFFFFFu, l0, 1);
    l0 += __shfl_xor_sync(0xFFFFFFFFu, l0, 2);
    l1 += __shfl_xor_sync(0xFFFFFFFFu, l1, 1);
    l1 += __shfl_xor_sync(0xFFFFFFFFu, l1, 2);
    const float inv0 = 1.f / l0;
    const float inv1 = 1.f / l1;

    float* o0 = out + (bbase + r0) * DIM + headoff;
    float* o1 = out + (bbase + r1) * DIM + headoff;
#pragma unroll
    for (int nt = 0; nt < 8; nt++) {
        float2 w0, w1;
        w0.x = of[nt][0] * inv0; w0.y = of[nt][1] * inv0;
        w1.x = of[nt][2] * inv1; w1.y = of[nt][3] * inv1;
        *(float2*)(o0 + 8 * nt + 2 * tg) = w0;
        *(float2*)(o1 + 8 * nt + 2 * tg) = w1;
    }
}

// ---------------------------------------------------------------------------
// Launch
// ---------------------------------------------------------------------------
extern "C" void kernel_launch(void* const* d_in, const int* in_sizes, int n_in,
                              void* d_out, int out_size)
{
    const float* x   = (const float*)d_in[0];
    const float* Wq  = (const float*)d_in[1];
    const float* bq  = (const float*)d_in[2];
    const float* Wk  = (const float*)d_in[3];
    const float* bk  = (const float*)d_in[4];
    const float* Wv  = (const float*)d_in[5];
    const float* bv  = (const float*)d_in[6];
    const float* Wo  = (const float*)d_in[7];
    const float* bo  = (const float*)d_in[8];
    const float* nqw = (const float*)d_in[9];
    const float* nkw = (const float*)d_in[10];
    float* out = (float*)d_out;

    float *dq, *dk, *dv, *dattn;
    cudaGetSymbolAddress((void**)&dq,    g_q);
    cudaGetSymbolAddress((void**)&dk,    g_k);
    cudaGetSymbolAddress((void**)&dv,    g_v);
    cudaGetSymbolAddress((void**)&dattn, g_attn);

    dim3 qkvgrid(DIM / GBN, MROWS / GBM, 3);   // (8, 32, 3)
    gemm_qkv_kernel<<<qkvgrid, 256>>>(x, Wq, bq, Wk, bk, Wv, bv, dq, dk, dv);

    rmsnorm_kernel<<<MROWS, 256>>>(dq, nqw);
    rmsnorm_kernel<<<MROWS, 256>>>(dk, nkw);

    dim3 agrid(SEQ / 64, NHEAD, BATCH);
    attn_tc_kernel<<<agrid, 128>>>(dq, dk, dv, dattn);

    dim3 ggrid(DIM / GBN, MROWS / GBM);
    gemm_tf32_kernel<<<ggrid, 256>>>(dattn, Wo, bo, out, MROWS, DIM, DIM);
}

// round 5
// speedup vs baseline: 3.0231x; 1.1518x over previous
#include <cuda_runtime.h>
#include <cuda_bf16.h>
#include <math.h>
#include <stdint.h>

// Problem constants
#define BATCH 2
#define SEQ   2048
#define DIM   1024
#define NHEAD 16
#define HDIM  64
#define MROWS (BATCH*SEQ)   // 4096

// Scratch buffers (allocation-free rule: static device globals)
__device__ float g_q[MROWS * DIM];
__device__ float g_k[MROWS * DIM];
__device__ float g_v[MROWS * DIM];
__device__ float g_attn[MROWS * DIM];

__device__ __forceinline__ uint32_t f2tf32(float f) {
    uint32_t u;
    asm("cvt.rna.tf32.f32 %0, %1;" : "=r"(u) : "f"(f));
    return u;
}

__device__ __forceinline__ float ex2(float x) {
    float y;
    asm("ex2.approx.f32 %0, %1;" : "=f"(y) : "f"(x));
    return y;
}

__device__ __forceinline__ void mma_tf32(float* d, const uint32_t* a,
                                         const uint32_t* b, const float* c) {
    asm volatile(
        "mma.sync.aligned.m16n8k8.row.col.f32.tf32.tf32.f32 "
        "{%0,%1,%2,%3}, {%4,%5,%6,%7}, {%8,%9}, {%10,%11,%12,%13};\n"
        : "=f"(d[0]), "=f"(d[1]), "=f"(d[2]), "=f"(d[3])
        : "r"(a[0]), "r"(a[1]), "r"(a[2]), "r"(a[3]),
          "r"(b[0]), "r"(b[1]),
          "f"(c[0]), "f"(c[1]), "f"(c[2]), "f"(c[3]));
}

// ---------------------------------------------------------------------------
// tf32 tensor-core GEMM: C[M,N] = A[M,K] @ W[N,K]^T + bias[N]
// Tiles: 128x128x32, 256 threads = 8 warps (2 M x 4 N), 64x32 per warp.
// ---------------------------------------------------------------------------
#define GBM 128
#define GBN 128
#define GBK 32
#define KSTRIDE 36

__device__ __forceinline__ void gemm_tf32_body(
    const float* __restrict__ A, const float* __restrict__ W,
    const float* __restrict__ bias, float* __restrict__ C,
    int M, int N, int K, int bx, int by)
{
    __shared__ uint32_t As[GBM][KSTRIDE];
    __shared__ uint32_t Bs[GBN][KSTRIDE];

    const int tid  = threadIdx.x;
    const int bm   = by * GBM;
    const int bn   = bx * GBN;
    const int warp = tid >> 5;
    const int lane = tid & 31;
    const int wm   = (warp >> 2) * 64;
    const int wn   = (warp & 3) * 32;
    const int gr   = lane >> 2;
    const int tg   = lane & 3;

    const int lrow = tid >> 1;
    const int lcol = (tid & 1) * 16;
    const float* ag = A + (size_t)(bm + lrow) * K + lcol;
    const float* wg = W + (size_t)(bn + lrow) * K + lcol;

    float acc[4][4][4];
#pragma unroll
    for (int i = 0; i < 4; i++)
#pragma unroll
        for (int j = 0; j < 4; j++)
#pragma unroll
            for (int c = 0; c < 4; c++) acc[i][j][c] = 0.f;

    float4 ra[4], rb[4];
#pragma unroll
    for (int c = 0; c < 4; c++) {
        ra[c] = *(const float4*)(ag + c * 4);
        rb[c] = *(const float4*)(wg + c * 4);
    }

    for (int k0 = 0; k0 < K; k0 += GBK) {
        __syncthreads();
#pragma unroll
        for (int c = 0; c < 4; c++) {
            uint32_t* ap = &As[lrow][lcol + c * 4];
            ap[0] = f2tf32(ra[c].x); ap[1] = f2tf32(ra[c].y);
            ap[2] = f2tf32(ra[c].z); ap[3] = f2tf32(ra[c].w);
            uint32_t* bp = &Bs[lrow][lcol + c * 4];
            bp[0] = f2tf32(rb[c].x); bp[1] = f2tf32(rb[c].y);
            bp[2] = f2tf32(rb[c].z); bp[3] = f2tf32(rb[c].w);
        }
        __syncthreads();

        if (k0 + GBK < K) {
#pragma unroll
            for (int c = 0; c < 4; c++) {
                ra[c] = *(const float4*)(ag + k0 + GBK + c * 4);
                rb[c] = *(const float4*)(wg + k0 + GBK + c * 4);
            }
        }

#pragma unroll
        for (int ks = 0; ks < 4; ks++) {
            const int kk = ks * 8;
            uint32_t af[4][4], bf[4][2];
#pragma unroll
            for (int i = 0; i < 4; i++) {
                const int r = wm + i * 16 + gr;
                af[i][0] = As[r][kk + tg];
                af[i][1] = As[r + 8][kk + tg];
                af[i][2] = As[r][kk + tg + 4];
                af[i][3] = As[r + 8][kk + tg + 4];
            }
#pragma unroll
            for (int j = 0; j < 4; j++) {
                const int n = wn + j * 8 + gr;
                bf[j][0] = Bs[n][kk + tg];
                bf[j][1] = Bs[n][kk + tg + 4];
            }
#pragma unroll
            for (int i = 0; i < 4; i++)
#pragma unroll
                for (int j = 0; j < 4; j++)
                    mma_tf32(acc[i][j], af[i], bf[j], acc[i][j]);
        }
    }

#pragma unroll
    for (int i = 0; i < 4; i++) {
#pragma unroll
        for (int j = 0; j < 4; j++) {
            const int row = bm + wm + i * 16 + gr;
            const int col = bn + wn + j * 8 + 2 * tg;
            const float2 b01 = *(const float2*)(bias + col);
            float2 o0, o1;
            o0.x = acc[i][j][0] + b01.x;
            o0.y = acc[i][j][1] + b01.y;
            o1.x = acc[i][j][2] + b01.x;
            o1.y = acc[i][j][3] + b01.y;
            *(float2*)(C + (size_t)row * N + col)       = o0;
            *(float2*)(C + (size_t)(row + 8) * N + col) = o1;
        }
    }
}

__global__ __launch_bounds__(256) void gemm_tf32_kernel(
    const float* __restrict__ A, const float* __restrict__ W,
    const float* __restrict__ bias, float* __restrict__ C,
    int M, int N, int K)
{
    gemm_tf32_body(A, W, bias, C, M, N, K, blockIdx.x, blockIdx.y);
}

// Fused QKV: blockIdx.z selects which projection (better wave packing)
__global__ __launch_bounds__(256) void gemm_qkv_kernel(
    const float* __restrict__ A,
    const float* __restrict__ Wq, const float* __restrict__ bq,
    const float* __restrict__ Wk, const float* __restrict__ bk,
    const float* __restrict__ Wv, const float* __restrict__ bv,
    float* __restrict__ Cq, float* __restrict__ Ck, float* __restrict__ Cv)
{
    const float* W; const float* b; float* C;
    if (blockIdx.z == 0)      { W = Wq; b = bq; C = Cq; }
    else if (blockIdx.z == 1) { W = Wk; b = bk; C = Ck; }
    else                      { W = Wv; b = bv; C = Cv; }
    gemm_tf32_body(A, W, b, C, MROWS, DIM, DIM, blockIdx.x, blockIdx.y);
}

// ---------------------------------------------------------------------------
// RMSNorm in-place over rows of length DIM=1024. One block (256 thr) per row.
// ---------------------------------------------------------------------------
__global__ __launch_bounds__(256) void rmsnorm_kernel(
    float* __restrict__ x, const float* __restrict__ w)
{
    const int row = blockIdx.x;
    float* p = x + (size_t)row * DIM;
    const int t = threadIdx.x;

    float4 v = *(const float4*)(p + t * 4);
    float ss = v.x * v.x + v.y * v.y + v.z * v.z + v.w * v.w;

#pragma unroll
    for (int off = 16; off > 0; off >>= 1)
        ss += __shfl_xor_sync(0xFFFFFFFFu, ss, off);

    __shared__ float red[8];
    if ((t & 31) == 0) red[t >> 5] = ss;
    __syncthreads();
    float total;
    {
        float r = (t < 8) ? red[t] : 0.f;
#pragma unroll
        for (int off = 4; off > 0; off >>= 1)
            r += __shfl_xor_sync(0xFFFFFFFFu, r, off);
        if (t == 0) red[0] = r;
    }
    __syncthreads();
    total = red[0];

    const float norm = rsqrtf(total * (1.0f / DIM) + 1e-6f);
    const float4 w4 = *(const float4*)(w + t * 4);
    v.x = v.x * norm * w4.x;
    v.y = v.y * norm * w4.y;
    v.z = v.z * norm * w4.z;
    v.w = v.w * norm * w4.w;
    *(float4*)(p + t * 4) = v;
}

// ---------------------------------------------------------------------------
// Tensor-core flash attention v2 (tf32 mma.m16n8k8).
// Grid (SEQ/64, NHEAD, BATCH), 128 threads = 4 warps, 16 Q-rows per warp.
// Layout tricks (perm8(l) = 2(l%4)+(l/4) within groups of 8):
//  - Ks rows (keys) permuted  -> S accumulator layout == P A-fragment layout.
//  - Q/K head-dim cols permuted -> fragment pairs (tg, tg+4) contiguous: LDS.64.
//  - V stored TRANSPOSED (hd x keys) with key cols permuted -> LDS.64 too.
//  - Q tile lives in smem (fragments reloaded per tile) -> regs ~<=125, 4 blk/SM.
//  - exp2-domain softmax: 0.125*log2e folded into Q scale, raw ex2.approx.
// All strides 72 words (==8 mod 32): all fragment loads bank-conflict-free.
// ---------------------------------------------------------------------------
#define ASTR 72

__global__ __launch_bounds__(128, 4) void attn_tc_kernel(
    const float* __restrict__ q, const float* __restrict__ k,
    const float* __restrict__ v, float* __restrict__ out)
{
    extern __shared__ uint32_t sm[];
    uint32_t* Qs = sm;                 // [64][ASTR]
    uint32_t* Ks = sm + 64 * ASTR;     // [64][ASTR]
    uint32_t* Vt = sm + 128 * ASTR;    // [64][ASTR]  (hd-major, key cols permuted)

    const int tid  = threadIdx.x;
    const int warp = tid >> 5;
    const int lane = tid & 31;
    const int gr   = lane >> 2;
    const int tg   = lane & 3;
    const int h    = blockIdx.y;
    const int b    = blockIdx.z;

    const int qrow0   = blockIdx.x * 64;           // first Q row of block
    const size_t headoff = (size_t)h * HDIM;
    const size_t bbase   = (size_t)b * SEQ;
    const float SCALE = 0.125f * 1.4426950408889634f;   // 1/sqrt(64) * log2(e)

    // load Q tile -> smem (scaled, tf32, hd cols permuted)
    for (int i = tid; i < 64 * 16; i += 128) {
        const int r  = i >> 4;
        const int c4 = i & 15;
        const float4 qv = *(const float4*)(q + (bbase + qrow0 + r) * DIM + headoff + c4 * 4);
        uint32_t* dst = &Qs[r * ASTR + 8 * (c4 >> 1) + (c4 & 1)];
        dst[0] = f2tf32(qv.x * SCALE);
        dst[2] = f2tf32(qv.y * SCALE);
        dst[4] = f2tf32(qv.z * SCALE);
        dst[6] = f2tf32(qv.w * SCALE);
    }

    const int qr = warp * 16 + gr;     // this thread's first Q row (local)

    float of[8][4];
#pragma unroll
    for (int nt = 0; nt < 8; nt++)
#pragma unroll
        for (int c = 0; c < 4; c++) of[nt][c] = 0.f;

    float m0 = -1e30f, m1 = -1e30f, l0 = 0.f, l1 = 0.f;

    for (int k0 = 0; k0 < SEQ; k0 += 64) {
        __syncthreads();   // previous-tile reads done (also covers Qs on iter 0)

        // K tile: rows key-permuted, cols hd-permuted
        for (int i = tid; i < 64 * 16; i += 128) {
            const int r  = i >> 4;
            const int c4 = i & 15;
            const int pr = (r & ~7) | (2 * (r & 3) + ((r >> 2) & 1));
            const float4 kv = *(const float4*)(k + (bbase + k0 + r) * DIM + headoff + c4 * 4);
            uint32_t* dst = &Ks[pr * ASTR + 8 * (c4 >> 1) + (c4 & 1)];
            dst[0] = f2tf32(kv.x);
            dst[2] = f2tf32(kv.y);
            dst[4] = f2tf32(kv.z);
            dst[6] = f2tf32(kv.w);
        }
        // V tile transposed: Vt[hd][key-col permuted]
        for (int i = tid; i < 64 * 16; i += 128) {
            const int c4 = i >> 6;          // 0..15 (hd chunk)
            const int r  = i & 63;          // key (lane-major -> conflict-free STS)
            const float4 vv = *(const float4*)(v + (bbase + k0 + r) * DIM + headoff + c4 * 4);
            const int pc = 8 * (r >> 3) + 2 * (r & 3) + ((r >> 2) & 1);
            Vt[(4 * c4 + 0) * ASTR + pc] = f2tf32(vv.x);
            Vt[(4 * c4 + 1) * ASTR + pc] = f2tf32(vv.y);
            Vt[(4 * c4 + 2) * ASTR + pc] = f2tf32(vv.z);
            Vt[(4 * c4 + 3) * ASTR + pc] = f2tf32(vv.w);
        }
        __syncthreads();

        // S = Q @ K^T (16 rows x 64 keys per warp), exp2 domain
        float sacc[8][4];
#pragma unroll
        for (int nt = 0; nt < 8; nt++)
#pragma unroll
            for (int c = 0; c < 4; c++) sacc[nt][c] = 0.f;

#pragma unroll
        for (int j = 0; j < 8; j++) {
            const uint2 q0 = *(const uint2*)&Qs[qr * ASTR + 8 * j + 2 * tg];
            const uint2 q1 = *(const uint2*)&Qs[(qr + 8) * ASTR + 8 * j + 2 * tg];
            uint32_t a[4] = {q0.x, q1.x, q0.y, q1.y};
#pragma unroll
            for (int nt = 0; nt < 8; nt++) {
                const uint2 kb = *(const uint2*)&Ks[(8 * nt + gr) * ASTR + 8 * j + 2 * tg];
                mma_tf32(sacc[nt], a, (const uint32_t*)&kb, sacc[nt]);
            }
        }

        // online softmax (log2 domain)
        float cm0 = -1e30f, cm1 = -1e30f;
#pragma unroll
        for (int nt = 0; nt < 8; nt++) {
            cm0 = fmaxf(cm0, fmaxf(sacc[nt][0], sacc[nt][1]));
            cm1 = fmaxf(cm1, fmaxf(sacc[nt][2], sacc[nt][3]));
        }
        cm0 = fmaxf(cm0, __shfl_xor_sync(0xFFFFFFFFu, cm0, 1));
        cm0 = fmaxf(cm0, __shfl_xor_sync(0xFFFFFFFFu, cm0, 2));
        cm1 = fmaxf(cm1, __shfl_xor_sync(0xFFFFFFFFu, cm1, 1));
        cm1 = fmaxf(cm1, __shfl_xor_sync(0xFFFFFFFFu, cm1, 2));

        const float mn0 = fmaxf(m0, cm0);
        const float mn1 = fmaxf(m1, cm1);
        const float a0 = ex2(m0 - mn0);
        const float a1 = ex2(m1 - mn1);
        m0 = mn0; m1 = mn1;
        l0 *= a0; l1 *= a1;
#pragma unroll
        for (int nt = 0; nt < 8; nt++) {
            of[nt][0] *= a0; of[nt][1] *= a0;
            of[nt][2] *= a1; of[nt][3] *= a1;
        }

        // O += P @ V ; P built per key-chunk from sacc (layout == A-fragment)
#pragma unroll
        for (int j = 0; j < 8; j++) {
            uint32_t a[4];
            a[0] = f2tf32(ex2(sacc[j][0] - m0));
            a[1] = f2tf32(ex2(sacc[j][2] - m1));
            a[2] = f2tf32(ex2(sacc[j][1] - m0));
            a[3] = f2tf32(ex2(sacc[j][3] - m1));
            // accumulate l from the tf32-rounded values (num/denom consistent)
            l0 += __uint_as_float(a[0]) + __uint_as_float(a[2]);
            l1 += __uint_as_float(a[1]) + __uint_as_float(a[3]);
#pragma unroll
            for (int nt = 0; nt < 8; nt++) {
                const uint2 vb = *(const uint2*)&Vt[(8 * nt + gr) * ASTR + 8 * j + 2 * tg];
                mma_tf32(of[nt], a, (const uint32_t*)&vb, of[nt]);
            }
        }
    }

    // finalize: reduce l across quad, normalize, store
    l0 += __shfl_xor_sync(0xFFFFFFFFu, l0, 1);
    l0 += __shfl_xor_sync(0xFFFFFFFFu, l0, 2);
    l1 += __shfl_xor_sync(0xFFFFFFFFu, l1, 1);
    l1 += __shfl_xor_sync(0xFFFFFFFFu, l1, 2);
    const float inv0 = 1.f / l0;
    const float inv1 = 1.f / l1;

    float* o0 = out + (bbase + qrow0 + qr) * DIM + headoff;
    float* o1 = out + (bbase + qrow0 + qr + 8) * DIM + headoff;
#pragma unroll
    for (int nt = 0; nt < 8; nt++) {
        float2 w0, w1;
        w0.x = of[nt][0] * inv0; w0.y = of[nt][1] * inv0;
        w1.x = of[nt][2] * inv1; w1.y = of[nt][3] * inv1;
        *(float2*)(o0 + 8 * nt + 2 * tg) = w0;
        *(float2*)(o1 + 8 * nt + 2 * tg) = w1;
    }
}

// ---------------------------------------------------------------------------
// Launch
// ---------------------------------------------------------------------------
extern "C" void kernel_launch(void* const* d_in, const int* in_sizes, int n_in,
                              void* d_out, int out_size)
{
    const float* x   = (const float*)d_in[0];
    const float* Wq  = (const float*)d_in[1];
    const float* bq  = (const float*)d_in[2];
    const float* Wk  = (const float*)d_in[3];
    const float* bk  = (const float*)d_in[4];
    const float* Wv  = (const float*)d_in[5];
    const float* bv  = (const float*)d_in[6];
    const float* Wo  = (const float*)d_in[7];
    const float* bo  = (const float*)d_in[8];
    const float* nqw = (const float*)d_in[9];
    const float* nkw = (const float*)d_in[10];
    float* out = (float*)d_out;

    float *dq, *dk, *dv, *dattn;
    cudaGetSymbolAddress((void**)&dq,    g_q);
    cudaGetSymbolAddress((void**)&dk,    g_k);
    cudaGetSymbolAddress((void**)&dv,    g_v);
    cudaGetSymbolAddress((void**)&dattn, g_attn);

    dim3 qkvgrid(DIM / GBN, MROWS / GBM, 3);   // (8, 32, 3)
    gemm_qkv_kernel<<<qkvgrid, 256>>>(x, Wq, bq, Wk, bk, Wv, bv, dq, dk, dv);

    rmsnorm_kernel<<<MROWS, 256>>>(dq, nqw);
    rmsnorm_kernel<<<MROWS, 256>>>(dk, nkw);

    const int attn_smem = 3 * 64 * ASTR * 4;   // 55296 bytes
    cudaFuncSetAttribute(attn_tc_kernel,
                         cudaFuncAttributeMaxDynamicSharedMemorySize, attn_smem);
    dim3 agrid(SEQ / 64, NHEAD, BATCH);
    attn_tc_kernel<<<agrid, 128, attn_smem>>>(dq, dk, dv, dattn);

    dim3 ggrid(DIM / GBN, MROWS / GBM);
    gemm_tf32_kernel<<<ggrid, 256>>>(dattn, Wo, bo, out, MROWS, DIM, DIM);
}

// round 6
// speedup vs baseline: 3.8883x; 1.2862x over previous
#include <cuda_runtime.h>
#include <cuda_bf16.h>
#include <math.h>
#include <stdint.h>

// Problem constants
#define BATCH 2
#define SEQ   2048
#define DIM   1024
#define NHEAD 16
#define HDIM  64
#define MROWS (BATCH*SEQ)   // 4096

// Scratch buffers (allocation-free rule: static device globals)
__device__ float    g_q[MROWS * DIM];
__device__ float    g_k[MROWS * DIM];
__device__ float    g_v[MROWS * DIM];
__device__ float    g_attn[MROWS * DIM];
__device__ uint32_t g_qp[MROWS * DIM];           // tf32 packed Q [b][h][s][hdperm]
__device__ uint32_t g_kp[MROWS * DIM];           // tf32 packed K [b][h][sperm][hdperm]
__device__ uint32_t g_vt[MROWS * DIM];           // tf32 packed V [b][h][hd][keyperm]

__device__ __forceinline__ uint32_t f2tf32(float f) {
    uint32_t u;
    asm("cvt.rna.tf32.f32 %0, %1;" : "=r"(u) : "f"(f));
    return u;
}

__device__ __forceinline__ float ex2(float x) {
    float y;
    asm("ex2.approx.f32 %0, %1;" : "=f"(y) : "f"(x));
    return y;
}

__device__ __forceinline__ void mma_tf32(float* d, const uint32_t* a,
                                         const uint32_t* b, const float* c) {
    asm volatile(
        "mma.sync.aligned.m16n8k8.row.col.f32.tf32.tf32.f32 "
        "{%0,%1,%2,%3}, {%4,%5,%6,%7}, {%8,%9}, {%10,%11,%12,%13};\n"
        : "=f"(d[0]), "=f"(d[1]), "=f"(d[2]), "=f"(d[3])
        : "r"(a[0]), "r"(a[1]), "r"(a[2]), "r"(a[3]),
          "r"(b[0]), "r"(b[1]),
          "f"(c[0]), "f"(c[1]), "f"(c[2]), "f"(c[3]));
}

__device__ __forceinline__ void cp_async16(uint32_t sm_addr, const void* gptr) {
    asm volatile("cp.async.cg.shared.global [%0], [%1], 16;\n"
                 :: "r"(sm_addr), "l"(gptr));
}

// perm within groups of 8: logical l -> 2*(l%4) + (l/4)
__device__ __forceinline__ int perm8(int l) {
    return (l & ~7) | (2 * (l & 3)) | ((l >> 2) & 1);
}

// ---------------------------------------------------------------------------
// tf32 tensor-core GEMM: C[M,N] = A[M,K] @ W[N,K]^T + bias[N]
// Tiles: 128x128x32, 256 threads = 8 warps (2 M x 4 N), 64x32 per warp.
// ---------------------------------------------------------------------------
#define GBM 128
#define GBN 128
#define GBK 32
#define KSTRIDE 36

__device__ __forceinline__ void gemm_tf32_body(
    const float* __restrict__ A, const float* __restrict__ W,
    const float* __restrict__ bias, float* __restrict__ C,
    int M, int N, int K, int bx, int by)
{
    __shared__ uint32_t As[GBM][KSTRIDE];
    __shared__ uint32_t Bs[GBN][KSTRIDE];

    const int tid  = threadIdx.x;
    const int bm   = by * GBM;
    const int bn   = bx * GBN;
    const int warp = tid >> 5;
    const int lane = tid & 31;
    const int wm   = (warp >> 2) * 64;
    const int wn   = (warp & 3) * 32;
    const int gr   = lane >> 2;
    const int tg   = lane & 3;

    const int lrow = tid >> 1;
    const int lcol = (tid & 1) * 16;
    const float* ag = A + (size_t)(bm + lrow) * K + lcol;
    const float* wg = W + (size_t)(bn + lrow) * K + lcol;

    float acc[4][4][4];
#pragma unroll
    for (int i = 0; i < 4; i++)
#pragma unroll
        for (int j = 0; j < 4; j++)
#pragma unroll
            for (int c = 0; c < 4; c++) acc[i][j][c] = 0.f;

    float4 ra[4], rb[4];
#pragma unroll
    for (int c = 0; c < 4; c++) {
        ra[c] = *(const float4*)(ag + c * 4);
        rb[c] = *(const float4*)(wg + c * 4);
    }

    for (int k0 = 0; k0 < K; k0 += GBK) {
        __syncthreads();
#pragma unroll
        for (int c = 0; c < 4; c++) {
            uint32_t* ap = &As[lrow][lcol + c * 4];
            ap[0] = f2tf32(ra[c].x); ap[1] = f2tf32(ra[c].y);
            ap[2] = f2tf32(ra[c].z); ap[3] = f2tf32(ra[c].w);
            uint32_t* bp = &Bs[lrow][lcol + c * 4];
            bp[0] = f2tf32(rb[c].x); bp[1] = f2tf32(rb[c].y);
            bp[2] = f2tf32(rb[c].z); bp[3] = f2tf32(rb[c].w);
        }
        __syncthreads();

        if (k0 + GBK < K) {
#pragma unroll
            for (int c = 0; c < 4; c++) {
                ra[c] = *(const float4*)(ag + k0 + GBK + c * 4);
                rb[c] = *(const float4*)(wg + k0 + GBK + c * 4);
            }
        }

#pragma unroll
        for (int ks = 0; ks < 4; ks++) {
            const int kk = ks * 8;
            uint32_t af[4][4], bf[4][2];
#pragma unroll
            for (int i = 0; i < 4; i++) {
                const int r = wm + i * 16 + gr;
                af[i][0] = As[r][kk + tg];
                af[i][1] = As[r + 8][kk + tg];
                af[i][2] = As[r][kk + tg + 4];
                af[i][3] = As[r + 8][kk + tg + 4];
            }
#pragma unroll
            for (int j = 0; j < 4; j++) {
                const int n = wn + j * 8 + gr;
                bf[j][0] = Bs[n][kk + tg];
                bf[j][1] = Bs[n][kk + tg + 4];
            }
#pragma unroll
            for (int i = 0; i < 4; i++)
#pragma unroll
                for (int j = 0; j < 4; j++)
                    mma_tf32(acc[i][j], af[i], bf[j], acc[i][j]);
        }
    }

#pragma unroll
    for (int i = 0; i < 4; i++) {
#pragma unroll
        for (int j = 0; j < 4; j++) {
            const int row = bm + wm + i * 16 + gr;
            const int col = bn + wn + j * 8 + 2 * tg;
            const float2 b01 = *(const float2*)(bias + col);
            float2 o0, o1;
            o0.x = acc[i][j][0] + b01.x;
            o0.y = acc[i][j][1] + b01.y;
            o1.x = acc[i][j][2] + b01.x;
            o1.y = acc[i][j][3] + b01.y;
            *(float2*)(C + (size_t)row * N + col)       = o0;
            *(float2*)(C + (size_t)(row + 8) * N + col) = o1;
        }
    }
}

__global__ __launch_bounds__(256) void gemm_tf32_kernel(
    const float* __restrict__ A, const float* __restrict__ W,
    const float* __restrict__ bias, float* __restrict__ C,
    int M, int N, int K)
{
    gemm_tf32_body(A, W, bias, C, M, N, K, blockIdx.x, blockIdx.y);
}

__global__ __launch_bounds__(256) void gemm_qkv_kernel(
    const float* __restrict__ A,
    const float* __restrict__ Wq, const float* __restrict__ bq,
    const float* __restrict__ Wk, const float* __restrict__ bk,
    const float* __restrict__ Wv, const float* __restrict__ bv,
    float* __restrict__ Cq, float* __restrict__ Ck, float* __restrict__ Cv)
{
    const float* W; const float* b; float* C;
    if (blockIdx.z == 0)      { W = Wq; b = bq; C = Cq; }
    else if (blockIdx.z == 1) { W = Wk; b = bk; C = Ck; }
    else                      { W = Wv; b = bv; C = Cv; }
    gemm_tf32_body(A, W, b, C, MROWS, DIM, DIM, blockIdx.x, blockIdx.y);
}

// ---------------------------------------------------------------------------
// Prepack Q/K: fused RMSNorm + tf32 cvt + head split + layout permutation.
// Q: scale (0.125*log2e) folded in.  K: key rows permuted within 8-groups.
// Output layout: [b][h][s(perm for K)][hd-perm], 64 words per row.
// Grid (MROWS, 2), 256 threads.
// ---------------------------------------------------------------------------
__global__ __launch_bounds__(256) void prepack_qk_kernel(
    const float* __restrict__ qin, const float* __restrict__ kin,
    const float* __restrict__ nqw, const float* __restrict__ nkw,
    uint32_t* __restrict__ qp, uint32_t* __restrict__ kp)
{
    const int row = blockIdx.x;
    const int isk = blockIdx.y;
    const float* src = (isk ? kin : qin) + (size_t)row * DIM;
    const float* w   = isk ? nkw : nqw;
    uint32_t* dstbuf = isk ? kp : qp;
    const int t = threadIdx.x;

    const float4 v = *(const float4*)(src + t * 4);
    float ss = v.x * v.x + v.y * v.y + v.z * v.z + v.w * v.w;
#pragma unroll
    for (int off = 16; off > 0; off >>= 1)
        ss += __shfl_xor_sync(0xFFFFFFFFu, ss, off);
    __shared__ float red[8];
    if ((t & 31) == 0) red[t >> 5] = ss;
    __syncthreads();
    {
        float r = (t < 8) ? red[t] : 0.f;
#pragma unroll
        for (int off = 4; off > 0; off >>= 1)
            r += __shfl_xor_sync(0xFFFFFFFFu, r, off);
        if (t == 0) red[0] = r;
    }
    __syncthreads();
    const float SCALE = 0.125f * 1.4426950408889634f;
    float norm = rsqrtf(red[0] * (1.0f / DIM) + 1e-6f);
    if (!isk) norm *= SCALE;

    const int b = row >> 11;
    const int s = row & 2047;
    const int srow = isk ? perm8(s) : s;
    const int d = t * 4;
    const int h = d >> 6;
    const float4 w4 = *(const float4*)(w + d);
    uint32_t* dst = dstbuf + (((size_t)b * NHEAD + h) * SEQ + srow) * 64;
    const float vals[4] = {v.x * norm * w4.x, v.y * norm * w4.y,
                           v.z * norm * w4.z, v.w * norm * w4.w};
#pragma unroll
    for (int e = 0; e < 4; e++) {
        const int l = (d & 63) + e;
        dst[perm8(l)] = f2tf32(vals[e]);
    }
}

// ---------------------------------------------------------------------------
// Prepack V: transpose to [b][h][hd][key-perm], tf32.
// Grid (SEQ/64, NHEAD, BATCH), 256 threads, smem transpose tile 64x64.
// ---------------------------------------------------------------------------
__global__ __launch_bounds__(256) void prepack_v_kernel(
    const float* __restrict__ vin, uint32_t* __restrict__ vt)
{
    __shared__ float ts[64][65];
    const int t  = threadIdx.x;
    const int k0 = blockIdx.x * 64;
    const int h  = blockIdx.y;
    const int b  = blockIdx.z;

    for (int i = t; i < 64 * 16; i += 256) {
        const int r  = i >> 4;
        const int c4 = i & 15;
        const float4 vv = *(const float4*)(
            vin + ((size_t)b * SEQ + k0 + r) * DIM + h * HDIM + c4 * 4);
        ts[r][c4 * 4 + 0] = vv.x;
        ts[r][c4 * 4 + 1] = vv.y;
        ts[r][c4 * 4 + 2] = vv.z;
        ts[r][c4 * 4 + 3] = vv.w;
    }
    __syncthreads();

    const int hd = t >> 2;
    uint32_t* dst = vt + (((size_t)b * NHEAD + h) * 64 + hd) * SEQ + k0;
#pragma unroll
    for (int g2 = 0; g2 < 2; g2++) {
        const int g = (t & 3) * 2 + g2;
        uint4 w0, w1;
        w0.x = f2tf32(ts[g * 8 + 0][hd]); w0.y = f2tf32(ts[g * 8 + 4][hd]);
        w0.z = f2tf32(ts[g * 8 + 1][hd]); w0.w = f2tf32(ts[g * 8 + 5][hd]);
        w1.x = f2tf32(ts[g * 8 + 2][hd]); w1.y = f2tf32(ts[g * 8 + 6][hd]);
        w1.z = f2tf32(ts[g * 8 + 3][hd]); w1.w = f2tf32(ts[g * 8 + 7][hd]);
        *(uint4*)(dst + g * 8)     = w0;
        *(uint4*)(dst + g * 8 + 4) = w1;
    }
}

// ---------------------------------------------------------------------------
// Tensor-core flash attention v3: prepacked tf32 operands, cp.async tile
// loads (zero STS/CVT in hot loop). Grid (SEQ/64, NHEAD, BATCH), 128 thr.
// All strides 72 words: fragment loads bank-conflict-free (measured R5).
// ---------------------------------------------------------------------------
#define ASTR 72

__global__ __launch_bounds__(128, 4) void attn_tc_kernel(
    const uint32_t* __restrict__ qp, const uint32_t* __restrict__ kp,
    const uint32_t* __restrict__ vt, float* __restrict__ out)
{
    extern __shared__ uint32_t sm[];
    uint32_t* Qs = sm;
    uint32_t* Ks = sm + 64 * ASTR;
    uint32_t* Vs = sm + 128 * ASTR;

    const int tid  = threadIdx.x;
    const int warp = tid >> 5;
    const int lane = tid & 31;
    const int gr   = lane >> 2;
    const int tg   = lane & 3;
    const int h    = blockIdx.y;
    const int b    = blockIdx.z;

    const int qrow0 = blockIdx.x * 64;
    const size_t bh = (size_t)b * NHEAD + h;
    const uint32_t* qbase = qp + (bh * SEQ + qrow0) * 64;
    const uint32_t* kbase = kp + bh * SEQ * 64;
    const uint32_t* vbase = vt + bh * 64 * SEQ;

    const uint32_t qs_a = (uint32_t)__cvta_generic_to_shared(Qs);
    const uint32_t ks_a = (uint32_t)__cvta_generic_to_shared(Ks);
    const uint32_t vs_a = (uint32_t)__cvta_generic_to_shared(Vs);

    // Q tile: 64 rows x 16 chunks of 16B
    for (int i = tid; i < 1024; i += 128) {
        const int r = i >> 4, ch = i & 15;
        cp_async16(qs_a + (r * ASTR + ch * 4) * 4, qbase + r * 64 + ch * 4);
    }

    const int qr = warp * 16 + gr;

    float of[8][4];
#pragma unroll
    for (int nt = 0; nt < 8; nt++)
#pragma unroll
        for (int c = 0; c < 4; c++) of[nt][c] = 0.f;

    float m0 = -1e30f, m1 = -1e30f, l0 = 0.f, l1 = 0.f;

    for (int k0 = 0; k0 < SEQ; k0 += 64) {
        __syncthreads();   // previous tile reads done
        for (int i = tid; i < 1024; i += 128) {
            const int r = i >> 4, ch = i & 15;
            cp_async16(ks_a + (r * ASTR + ch * 4) * 4,
                       kbase + (size_t)(k0 + r) * 64 + ch * 4);
        }
        for (int i = tid; i < 1024; i += 128) {
            const int r = i >> 4, ch = i & 15;   // r = hd row
            cp_async16(vs_a + (r * ASTR + ch * 4) * 4,
                       vbase + (size_t)r * SEQ + k0 + ch * 4);
        }
        asm volatile("cp.async.wait_all;\n" ::: "memory");
        __syncthreads();

        // S = Q @ K^T (16 rows x 64 keys per warp), exp2 domain
        float sacc[8][4];
#pragma unroll
        for (int nt = 0; nt < 8; nt++)
#pragma unroll
            for (int c = 0; c < 4; c++) sacc[nt][c] = 0.f;

#pragma unroll
        for (int j = 0; j < 8; j++) {
            const uint2 q0 = *(const uint2*)&Qs[qr * ASTR + 8 * j + 2 * tg];
            const uint2 q1 = *(const uint2*)&Qs[(qr + 8) * ASTR + 8 * j + 2 * tg];
            uint32_t a[4] = {q0.x, q1.x, q0.y, q1.y};
#pragma unroll
            for (int nt = 0; nt < 8; nt++) {
                const uint2 kb = *(const uint2*)&Ks[(8 * nt + gr) * ASTR + 8 * j + 2 * tg];
                mma_tf32(sacc[nt], a, (const uint32_t*)&kb, sacc[nt]);
            }
        }

        // online softmax (log2 domain)
        float cm0 = -1e30f, cm1 = -1e30f;
#pragma unroll
        for (int nt = 0; nt < 8; nt++) {
            cm0 = fmaxf(cm0, fmaxf(sacc[nt][0], sacc[nt][1]));
            cm1 = fmaxf(cm1, fmaxf(sacc[nt][2], sacc[nt][3]));
        }
        cm0 = fmaxf(cm0, __shfl_xor_sync(0xFFFFFFFFu, cm0, 1));
        cm0 = fmaxf(cm0, __shfl_xor_sync(0xFFFFFFFFu, cm0, 2));
        cm1 = fmaxf(cm1, __shfl_xor_sync(0xFFFFFFFFu, cm1, 1));
        cm1 = fmaxf(cm1, __shfl_xor_sync(0xFFFFFFFFu, cm1, 2));

        const float mn0 = fmaxf(m0, cm0);
        const float mn1 = fmaxf(m1, cm1);
        const float a0 = ex2(m0 - mn0);
        const float a1 = ex2(m1 - mn1);
        m0 = mn0; m1 = mn1;
        l0 *= a0; l1 *= a1;
#pragma unroll
        for (int nt = 0; nt < 8; nt++) {
            of[nt][0] *= a0; of[nt][1] *= a0;
            of[nt][2] *= a1; of[nt][3] *= a1;
        }

        // O += P @ V
#pragma unroll
        for (int j = 0; j < 8; j++) {
            uint32_t a[4];
            a[0] = f2tf32(ex2(sacc[j][0] - m0));
            a[1] = f2tf32(ex2(sacc[j][2] - m1));
            a[2] = f2tf32(ex2(sacc[j][1] - m0));
            a[3] = f2tf32(ex2(sacc[j][3] - m1));
            l0 += __uint_as_float(a[0]) + __uint_as_float(a[2]);
            l1 += __uint_as_float(a[1]) + __uint_as_float(a[3]);
#pragma unroll
            for (int nt = 0; nt < 8; nt++) {
                const uint2 vb = *(const uint2*)&Vs[(8 * nt + gr) * ASTR + 8 * j + 2 * tg];
                mma_tf32(of[nt], a, (const uint32_t*)&vb, of[nt]);
            }
        }
    }

    l0 += __shfl_xor_sync(0xFFFFFFFFu, l0, 1);
    l0 += __shfl_xor_sync(0xFFFFFFFFu, l0, 2);
    l1 += __shfl_xor_sync(0xFFFFFFFFu, l1, 1);
    l1 += __shfl_xor_sync(0xFFFFFFFFu, l1, 2);
    const float inv0 = 1.f / l0;
    const float inv1 = 1.f / l1;

    float* o0 = out + ((size_t)b * SEQ + qrow0 + qr) * DIM + h * HDIM;
    float* o1 = o0 + 8 * DIM;
#pragma unroll
    for (int nt = 0; nt < 8; nt++) {
        float2 w0, w1;
        w0.x = of[nt][0] * inv0; w0.y = of[nt][1] * inv0;
        w1.x = of[nt][2] * inv1; w1.y = of[nt][3] * inv1;
        *(float2*)(o0 + 8 * nt + 2 * tg) = w0;
        *(float2*)(o1 + 8 * nt + 2 * tg) = w1;
    }
}

// ---------------------------------------------------------------------------
// Launch
// ---------------------------------------------------------------------------
extern "C" void kernel_launch(void* const* d_in, const int* in_sizes, int n_in,
                              void* d_out, int out_size)
{
    const float* x   = (const float*)d_in[0];
    const float* Wq  = (const float*)d_in[1];
    const float* bq  = (const float*)d_in[2];
    const float* Wk  = (const float*)d_in[3];
    const float* bk  = (const float*)d_in[4];
    const float* Wv  = (const float*)d_in[5];
    const float* bv  = (const float*)d_in[6];
    const float* Wo  = (const float*)d_in[7];
    const float* bo  = (const float*)d_in[8];
    const float* nqw = (const float*)d_in[9];
    const float* nkw = (const float*)d_in[10];
    float* out = (float*)d_out;

    float *dq, *dk, *dv, *dattn;
    uint32_t *dqp, *dkp, *dvt;
    cudaGetSymbolAddress((void**)&dq,    g_q);
    cudaGetSymbolAddress((void**)&dk,    g_k);
    cudaGetSymbolAddress((void**)&dv,    g_v);
    cudaGetSymbolAddress((void**)&dattn, g_attn);
    cudaGetSymbolAddress((void**)&dqp,   g_qp);
    cudaGetSymbolAddress((void**)&dkp,   g_kp);
    cudaGetSymbolAddress((void**)&dvt,   g_vt);

    dim3 qkvgrid(DIM / GBN, MROWS / GBM, 3);
    gemm_qkv_kernel<<<qkvgrid, 256>>>(x, Wq, bq, Wk, bk, Wv, bv, dq, dk, dv);

    dim3 pgrid(MROWS, 2);
    prepack_qk_kernel<<<pgrid, 256>>>(dq, dk, nqw, nkw, dqp, dkp);
    dim3 vgrid(SEQ / 64, NHEAD, BATCH);
    prepack_v_kernel<<<vgrid, 256>>>(dv, dvt);

    const int attn_smem = 3 * 64 * ASTR * 4;   // 55296 bytes
    cudaFuncSetAttribute(attn_tc_kernel,
                         cudaFuncAttributeMaxDynamicSharedMemorySize, attn_smem);
    dim3 agrid(SEQ / 64, NHEAD, BATCH);
    attn_tc_kernel<<<agrid, 128, attn_smem>>>(dqp, dkp, dvt, dattn);

    dim3 ggrid(DIM / GBN, MROWS / GBM);
    gemm_tf32_kernel<<<ggrid, 256>>>(dattn, Wo, bo, out, MROWS, DIM, DIM);
}